// round 16
// baseline (speedup 1.0000x reference)
#include <cuda_runtime.h>
#include <cstdint>

#define DM   1024
#define DS   256
#define BATCH 8
#define LCH  8
#define SEQ  2048
#define NCH  (SEQ/LCH)      /* 256 */
#define MTOT (BATCH*SEQ)    /* 16384 */

typedef unsigned long long ull;

// ---------------- device scratch (no dynamic allocation allowed) -----------
__device__ float g_M [DS*DS];
__device__ float g_T0[DS*DS];
__device__ float g_T1[DS*DS];
__device__ float g_Ad[DS*DS];
__device__ float g_P [8][DS*DS];          // A_d^(8*2^s), s=0..7
__device__ float g_u [MTOT*DS];           // rows = b*SEQ + t
__device__ float g_f [BATCH*NCH*DS];      // chunk-local finals / KS ping
__device__ float g_g [BATCH*NCH*DS];      // KS pong
__device__ float g_hs[MTOT*DS];           // full hidden states

// ---------------- global spin barrier (co-resident grids only) --------------
__device__ unsigned g_barCnt = 0;
__device__ volatile unsigned g_barGen = 0;

__device__ __forceinline__ void gsync(unsigned nCTA){
    __syncthreads();
    if(threadIdx.x == 0){
        __threadfence();
        unsigned gen = g_barGen;
        if(atomicAdd(&g_barCnt, 1u) == nCTA - 1u){
            g_barCnt = 0;
            __threadfence();
            g_barGen = gen + 1u;
        } else {
            while(g_barGen == gen){ __nanosleep(32); }
        }
        __threadfence();
    }
    __syncthreads();
}

// ---------------- packed f32x2 helpers -------------------------------------
__device__ __forceinline__ ull pk2(float a, float b){
    ull r;
    asm("mov.b64 %0, {%1,%2};" : "=l"(r) : "f"(a), "f"(b));
    return r;
}
__device__ __forceinline__ void unpk2(ull v, float& a, float& b){
    asm("mov.b64 {%0,%1}, %2;" : "=f"(a), "=f"(b) : "l"(v));
}
__device__ __forceinline__ ull ffma2(ull a, ull b, ull c){
    ull d;
    asm("fma.rn.f32x2 %0, %1, %2, %3;" : "=l"(d) : "l"(a), "l"(b), "l"(c));
    return d;
}
__device__ __forceinline__ ull add2(ull a, ull b){
    ull d;
    asm("add.rn.f32x2 %0, %1, %2;" : "=l"(d) : "l"(a), "l"(b));
    return d;
}

// ---------------- tf32 helpers ----------------------------------------------
__device__ __forceinline__ uint32_t f2tf(float f){
    uint32_t r;
    asm("cvt.rna.tf32.f32 %0, %1;" : "=r"(r) : "f"(f));
    return r;
}
__device__ __forceinline__ void tfsplit(float f, float& h, float& l){
    uint32_t hb = f2tf(f);
    h = __uint_as_float(hb);
    l = __uint_as_float(f2tf(f - h));
}
#define MMA_TF32(d, a0,a1,a2,a3, b0,b1) \
    asm volatile("mma.sync.aligned.m16n8k8.row.col.f32.tf32.tf32.f32 " \
        "{%0,%1,%2,%3}, {%4,%5,%6,%7}, {%8,%9}, {%0,%1,%2,%3};" \
        : "+f"((d)[0]), "+f"((d)[1]), "+f"((d)[2]), "+f"((d)[3]) \
        : "r"(a0), "r"(a1), "r"(a2), "r"(a3), "r"(b0), "r"(b1))

__device__ __forceinline__ float* selmat(int s){
    switch(s){
        case 0: return g_M;
        case 1: return g_T0;
        case 2: return g_T1;
        case 3: return g_Ad;
        default: return g_P[s-4];
    }
}

// ---------------- fused expm + powers: 1 kernel, 13 matmul steps ------------
__constant__ int   c_sa[13]  = {0,4,4,3,1,2,4,5,6,7,8,9,10};
__constant__ int   c_sb[13]  = {0,1,2,3,1,2,4,5,6,7,8,9,10};
__constant__ int   c_sc[13]  = {4,2,3,1,2,4,5,6,7,8,9,10,11};
__constant__ float c_bet[13] = {0,1,1,0,0,0,0,0,0,0,0,0,0};
#define EXPM_CTAS 128u

__global__ void __launch_bounds__(256) k_expm_fused(const float* __restrict__ A){
    __shared__ float As[16][256];
    __shared__ float Bs[256][17];
    int tid = threadIdx.x, blk = blockIdx.x;
    #pragma unroll
    for(int e = 0; e < 2; e++){
        int i = blk*512 + e*256 + tid;
        float m = 0.1f * A[i];
        int r = i >> 8, cc = i & 255;
        float I = (r == cc) ? 1.0f : 0.0f;
        g_M [i] = m;
        g_Ad[i] = I + m;
        g_T0[i] = (1.0f/24.0f)*I + (1.0f/120.0f)*m;
        g_T1[i] = 0.5f*I + (1.0f/6.0f)*m;
    }
    gsync(EXPM_CTAS);
    for(int st = 0; st < 13; st++){
        const float* __restrict__ Am = selmat(c_sa[st]);
        const float* __restrict__ Bm = selmat(c_sb[st]);
        float* __restrict__ Cm = selmat(c_sc[st]);
        float beta = c_bet[st];
        #pragma unroll
        for(int half = 0; half < 2; half++){
            int T = blk*2 + half;
            int bi = (T >> 4)*16, bj = (T & 15)*16;
            #pragma unroll
            for(int it = 0; it < 4; it++){
                int idx = it*256 + tid;
                int r = idx >> 6, c4 = idx & 63;
                *(float4*)&As[r][c4*4] = *(const float4*)&Am[(bi+r)*DS + c4*4];
            }
            #pragma unroll
            for(int it = 0; it < 4; it++){
                int idx = it*256 + tid;
                int k = idx >> 2, c4 = idx & 3;
                float4 v = *(const float4*)&Bm[(size_t)k*DS + bj + c4*4];
                Bs[k][c4*4+0] = v.x; Bs[k][c4*4+1] = v.y;
                Bs[k][c4*4+2] = v.z; Bs[k][c4*4+3] = v.w;
            }
            __syncthreads();
            int r = tid >> 4, c = tid & 15;
            float a0=0.f, a1=0.f, a2=0.f, a3=0.f;
            #pragma unroll 8
            for(int k = 0; k < 256; k += 4){
                a0 += As[r][k  ]*Bs[k  ][c];
                a1 += As[r][k+1]*Bs[k+1][c];
                a2 += As[r][k+2]*Bs[k+2][c];
                a3 += As[r][k+3]*Bs[k+3][c];
            }
            float v = (a0+a1) + (a2+a3);
            int idx = (bi + r)*DS + bj + c;
            if(beta != 0.0f) v += Cm[idx];
            __syncthreads();
            Cm[idx] = v;
        }
        gsync(EXPM_CTAS);
    }
}

// ---------------- TF32 split-3 tensor GEMM: 128x128 tile, 256 thr -----------
// D = A@B with A,B fp32; 3 passes (Ah*Bh + Al*Bh + Ah*Bl) in tf32 mma.sync.
#define AP 20           /* A smem pitch (bank-conflict-free for frag loads) */
#define BP 136          /* B smem pitch */
template<int KDIM, int NDIM, bool EPI>
__global__ void __launch_bounds__(256,1) k_tgemm(const float* __restrict__ A,
                                                 const float* __restrict__ B,
                                                 float* __restrict__ Out,
                                                 const float* __restrict__ X,
                                                 const float* __restrict__ Dv){
    __shared__ float AsH[128*AP], AsL[128*AP];
    __shared__ float BsH[16*BP],  BsL[16*BP];
    int tid = threadIdx.x, wid = tid >> 5, lane = tid & 31;
    int row0 = blockIdx.y*128, col0 = blockIdx.x*128;

    // staging assignment: A tile 128x16 (8 elems/thread), B tile 16x128
    int am = tid >> 1, ak = (tid & 1)*8;
    int bk = tid >> 4, bn = (tid & 15)*8;
    const float* Ap0 = A + (size_t)(row0 + am)*KDIM + ak;
    const float* Bp0 = B + (size_t)bk*NDIM + col0 + bn;

    float ra[8], rb[8];
    *(float4*)&ra[0] = *(const float4*)(Ap0);
    *(float4*)&ra[4] = *(const float4*)(Ap0 + 4);
    *(float4*)&rb[0] = *(const float4*)(Bp0);
    *(float4*)&rb[4] = *(const float4*)(Bp0 + 4);
    #pragma unroll
    for(int e = 0; e < 8; e++){
        float h, l;
        tfsplit(ra[e], h, l);
        AsH[am*AP + ak + e] = h;  AsL[am*AP + ak + e] = l;
        tfsplit(rb[e], h, l);
        BsH[bk*BP + bn + e] = h;  BsL[bk*BP + bn + e] = l;
    }
    __syncthreads();

    float acc[16][4];
    #pragma unroll
    for(int t = 0; t < 16; t++)
        #pragma unroll
        for(int e = 0; e < 4; e++) acc[t][e] = 0.f;

    const int NT = KDIM/16;
    for(int kt = 0; kt < NT; kt++){
        if(kt + 1 < NT){
            const float* Ap = Ap0 + (kt+1)*16;
            const float* Bp = Bp0 + (size_t)(kt+1)*16*NDIM;
            *(float4*)&ra[0] = *(const float4*)(Ap);
            *(float4*)&ra[4] = *(const float4*)(Ap + 4);
            *(float4*)&rb[0] = *(const float4*)(Bp);
            *(float4*)&rb[4] = *(const float4*)(Bp + 4);
        }
        #pragma unroll
        for(int ks = 0; ks < 2; ks++){
            int r = lane >> 2, cq = lane & 3;
            int mA = wid*16 + r, cA = ks*8 + cq;
            uint32_t a0h = __float_as_uint(AsH[ mA    *AP + cA    ]);
            uint32_t a1h = __float_as_uint(AsH[(mA+8) *AP + cA    ]);
            uint32_t a2h = __float_as_uint(AsH[ mA    *AP + cA + 4]);
            uint32_t a3h = __float_as_uint(AsH[(mA+8) *AP + cA + 4]);
            uint32_t a0l = __float_as_uint(AsL[ mA    *AP + cA    ]);
            uint32_t a1l = __float_as_uint(AsL[(mA+8) *AP + cA    ]);
            uint32_t a2l = __float_as_uint(AsL[ mA    *AP + cA + 4]);
            uint32_t a3l = __float_as_uint(AsL[(mA+8) *AP + cA + 4]);
            int kb = ks*8 + cq, nb = lane >> 2;
            #pragma unroll
            for(int nt = 0; nt < 16; nt++){
                int off = nt*8 + nb;
                uint32_t b0h = __float_as_uint(BsH[ kb   *BP + off]);
                uint32_t b1h = __float_as_uint(BsH[(kb+4)*BP + off]);
                uint32_t b0l = __float_as_uint(BsL[ kb   *BP + off]);
                uint32_t b1l = __float_as_uint(BsL[(kb+4)*BP + off]);
                MMA_TF32(acc[nt], a0h,a1h,a2h,a3h, b0h,b1h);
                MMA_TF32(acc[nt], a0l,a1l,a2l,a3l, b0h,b1h);
                MMA_TF32(acc[nt], a0h,a1h,a2h,a3h, b0l,b1l);
            }
        }
        __syncthreads();
        if(kt + 1 < NT){
            #pragma unroll
            for(int e = 0; e < 8; e++){
                float h, l;
                tfsplit(ra[e], h, l);
                AsH[am*AP + ak + e] = h;  AsL[am*AP + ak + e] = l;
                tfsplit(rb[e], h, l);
                BsH[bk*BP + bn + e] = h;  BsL[bk*BP + bn + e] = l;
            }
            __syncthreads();
        }
    }

    // epilogue: c-frag layout (r = lane>>2, 2c = (lane&3)*2)
    int r = lane >> 2, cq = lane & 3;
    #pragma unroll
    for(int nt = 0; nt < 16; nt++){
        int m0 = row0 + wid*16 + r;
        int cb = col0 + nt*8 + 2*cq;
        float2 v0 = make_float2(acc[nt][0], acc[nt][1]);
        float2 v1 = make_float2(acc[nt][2], acc[nt][3]);
        if(EPI){
            float d0 = Dv[cb], d1 = Dv[cb+1];
            v0.x += X[(size_t)m0*NDIM + cb]*d0;
            v0.y += X[(size_t)m0*NDIM + cb + 1]*d1;
            v1.x += X[(size_t)(m0+8)*NDIM + cb]*d0;
            v1.y += X[(size_t)(m0+8)*NDIM + cb + 1]*d1;
        }
        *(float2*)&Out[(size_t)m0*NDIM + cb]     = v0;
        *(float2*)&Out[(size_t)(m0+8)*NDIM + cb] = v1;
    }
}

// ---------------- fused scan, 512 thr, LCH=8, pipelined matrix loads --------
#define MV(Mptr) do { \
    float a[8], an[8]; \
    _Pragma("unroll") \
    for(int k = 0; k < 8; k++) a[k] = (Mptr)[(i0+k)*DS + j]; \
    for(int ib = i0; ib < i0 + 128; ib += 8){ \
        if(ib + 8 < i0 + 128){ \
            _Pragma("unroll") \
            for(int k = 0; k < 8; k++) an[k] = (Mptr)[(ib+8+k)*DS + j]; \
        } \
        _Pragma("unroll") \
        for(int k = 0; k < 8; k++){ \
            ull aa = pk2(a[k], a[k]); \
            ulonglong2 hA = *(const ulonglong2*)&h2[ib+k][0]; \
            ulonglong2 hB = *(const ulonglong2*)&h2[ib+k][2]; \
            acc[0] = ffma2(hA.x, aa, acc[0]); \
            acc[1] = ffma2(hA.y, aa, acc[1]); \
            acc[2] = ffma2(hB.x, aa, acc[2]); \
            acc[3] = ffma2(hB.y, aa, acc[3]); \
        } \
        _Pragma("unroll") \
        for(int k = 0; k < 8; k++) a[k] = an[k]; \
    } } while(0)

__global__ void __launch_bounds__(512,2) k_scan_fused(const float* __restrict__ h0){
    __shared__ __align__(16) ull h2 [DS][4];
    __shared__ __align__(16) ull prt[DS][4];
    int tid = threadIdx.x;
    int j = tid & 255, half = tid >> 8;
    int i0 = half * 128;
    int c = blockIdx.x;
    ull acc[4];

    // ================= Phase A =================
    if(half == 0){
        if(c == 0){
            #pragma unroll
            for(int p = 0; p < 4; p++)
                h2[j][p] = pk2(h0[(2*p)*DS + j], h0[(2*p+1)*DS + j]);
        } else {
            #pragma unroll
            for(int p = 0; p < 4; p++) h2[j][p] = 0ULL;
        }
    }
    __syncthreads();
    for(int t = 0; t < LCH; t++){
        int tt = c*LCH + t;
        if(half == 0){
            #pragma unroll
            for(int p = 0; p < 4; p++)
                acc[p] = pk2(g_u[((size_t)(2*p)*SEQ   + tt)*DS + j],
                             g_u[((size_t)(2*p+1)*SEQ + tt)*DS + j]);
        } else {
            #pragma unroll
            for(int p = 0; p < 4; p++) acc[p] = 0ULL;
        }
        MV(g_Ad);
        if(half == 1){
            #pragma unroll
            for(int p = 0; p < 4; p++) prt[j][p] = acc[p];
        }
        __syncthreads();
        if(half == 0){
            #pragma unroll
            for(int p = 0; p < 4; p++) h2[j][p] = add2(acc[p], prt[j][p]);
        }
        __syncthreads();
    }
    if(half == 0){
        #pragma unroll
        for(int p = 0; p < 4; p++){
            float lo, hi; unpk2(h2[j][p], lo, hi);
            g_f[((2*p)*NCH   + c)*DS + j] = lo;
            g_f[((2*p+1)*NCH + c)*DS + j] = hi;
        }
    }
    gsync(NCH);

    // ================= Kogge-Stone: 8 stages over 256 chunks ================
    for(int s = 0; s < 8; s++){
        int d = 1 << s;
        const float* In  = (s & 1) ? g_g : g_f;
        float*       Out = (s & 1) ? g_f : g_g;
        const float* P = g_P[s];
        if(c < d){
            for(int e = tid; e < BATCH*DS; e += 512){
                int b = e >> 8, jj = e & 255;
                Out[(b*NCH + c)*DS + jj] = In[(b*NCH + c)*DS + jj];
            }
        } else {
            if(half == 0){
                #pragma unroll
                for(int p = 0; p < 4; p++)
                    h2[j][p] = pk2(In[((2*p)*NCH   + c - d)*DS + j],
                                   In[((2*p+1)*NCH + c - d)*DS + j]);
            }
            __syncthreads();
            if(half == 0){
                #pragma unroll
                for(int p = 0; p < 4; p++)
                    acc[p] = pk2(In[((2*p)*NCH   + c)*DS + j],
                                 In[((2*p+1)*NCH + c)*DS + j]);
            } else {
                #pragma unroll
                for(int p = 0; p < 4; p++) acc[p] = 0ULL;
            }
            MV(P);
            if(half == 1){
                #pragma unroll
                for(int p = 0; p < 4; p++) prt[j][p] = acc[p];
            }
            __syncthreads();
            if(half == 0){
                #pragma unroll
                for(int p = 0; p < 4; p++){
                    ull v = add2(acc[p], prt[j][p]);
                    float lo, hi; unpk2(v, lo, hi);
                    Out[((2*p)*NCH   + c)*DS + j] = lo;
                    Out[((2*p+1)*NCH + c)*DS + j] = hi;
                }
            }
        }
        gsync(NCH);
    }

    // ============ Phase C (boundaries in g_f after 8 stages) ================
    if(half == 0){
        if(c == 0){
            #pragma unroll
            for(int p = 0; p < 4; p++)
                h2[j][p] = pk2(h0[(2*p)*DS + j], h0[(2*p+1)*DS + j]);
        } else {
            #pragma unroll
            for(int p = 0; p < 4; p++)
                h2[j][p] = pk2(g_f[((2*p)*NCH   + c - 1)*DS + j],
                               g_f[((2*p+1)*NCH + c - 1)*DS + j]);
        }
    }
    __syncthreads();
    for(int t = 0; t < LCH; t++){
        int tt = c*LCH + t;
        if(half == 0){
            #pragma unroll
            for(int p = 0; p < 4; p++)
                acc[p] = pk2(g_u[((size_t)(2*p)*SEQ   + tt)*DS + j],
                             g_u[((size_t)(2*p+1)*SEQ + tt)*DS + j]);
        } else {
            #pragma unroll
            for(int p = 0; p < 4; p++) acc[p] = 0ULL;
        }
        MV(g_Ad);
        if(half == 1){
            #pragma unroll
            for(int p = 0; p < 4; p++) prt[j][p] = acc[p];
        }
        __syncthreads();
        if(half == 0){
            #pragma unroll
            for(int p = 0; p < 4; p++){
                ull v = add2(acc[p], prt[j][p]);
                h2[j][p] = v;
                float lo, hi; unpk2(v, lo, hi);
                g_hs[((size_t)(2*p)*SEQ   + tt)*DS + j] = lo;
                g_hs[((size_t)(2*p+1)*SEQ + tt)*DS + j] = hi;
            }
        }
        __syncthreads();
    }
}

// ---------------- stream fork infrastructure (created pre-baseline) ---------
static cudaStream_t g_s1;
static cudaEvent_t  g_evF, g_evP;
static int g_once = [](){
    cudaStreamCreateWithFlags(&g_s1, cudaStreamNonBlocking);
    cudaEventCreateWithFlags(&g_evF, cudaEventDisableTiming);
    cudaEventCreateWithFlags(&g_evP, cudaEventDisableTiming);
    return 0;
}();

// ---------------- launch ----------------------------------------------------
extern "C" void kernel_launch(void* const* d_in, const int* in_sizes, int n_in,
                              void* d_out, int out_size){
    const float* x  = (const float*)d_in[0];
    const float* A  = (const float*)d_in[1];
    const float* Bm = (const float*)d_in[2];
    const float* Cm = (const float*)d_in[3];
    const float* Dv = (const float*)d_in[4];
    const float* h0 = (const float*)d_in[5];
    float* y = (float*)d_out;

    void* pu  = nullptr;  cudaGetSymbolAddress(&pu,  g_u);
    void* phs = nullptr;  cudaGetSymbolAddress(&phs, g_hs);

    // fork: fused expm+powers on side stream, concurrent with u-GEMM
    cudaEventRecord(g_evF, 0);
    cudaStreamWaitEvent(g_s1, g_evF, 0);
    k_expm_fused<<<EXPM_CTAS, 256, 0, g_s1>>>(A);
    cudaEventRecord(g_evP, g_s1);

    // main stream: u = x @ B  (tf32 split-3 tensor GEMM)
    k_tgemm<DM, DS, false><<<dim3(DS/128, MTOT/128), 256>>>(
        x, Bm, (float*)pu, nullptr, nullptr);

    // join, then fused scan
    cudaStreamWaitEvent(0, g_evP, 0);
    k_scan_fused<<<NCH, 512>>>(h0);

    // y = hs @ C + x * D  (tf32 split-3 tensor GEMM; my launch #4 for ncu)
    k_tgemm<DS, DM, true><<<dim3(DM/128, MTOT/128), 256>>>(
        (const float*)phs, Cm, y, x, Dv);
}